// round 8
// baseline (speedup 1.0000x reference)
#include <cuda_runtime.h>

#define TLEN  640
#define DDIM  256
#define NH    64              // distinct harmonics (D / NUM_CH)
#define NWARP 8
#define NT    (TLEN / NWARP)  // 80 samples per warp chunk

typedef unsigned long long u64;

__device__ __forceinline__ u64 pk2(float lo, float hi) {
    u64 r; asm("mov.b64 %0, {%1,%2};" : "=l"(r) : "f"(lo), "f"(hi)); return r;
}
__device__ __forceinline__ void upk2(u64 v, float &lo, float &hi) {
    asm("mov.b64 {%0,%1}, %2;" : "=f"(lo), "=f"(hi) : "l"(v));
}
__device__ __forceinline__ u64 fma2(u64 a, u64 b, u64 c) {
    u64 d; asm("fma.rn.f32x2 %0, %1, %2, %3;" : "=l"(d) : "l"(a), "l"(b), "l"(c)); return d;
}

#define INV2PI 0.15915494309189535f
#define PI2_HI 6.28125f                    // 8-bit mantissa: k*PI2_HI exact for k small
#define PI2_LO 1.9353071795864769e-3f
#define T_WAV  6.25e-05f                   // fl(1/16000), matches reference arange*scalar

// Goertzel per (t-chunk, harmonic):  s_n = x_n + 2cos(d)*s_{n-1} - s_{n-2}
// y = s_{N-1} - e^{-id} s_{N-2};  C + iS = e^{i psi_last} * conj(y)
// out[sb,dd] = a[dd] * ( cos(phi)*S_h + sin(phi)*C_h ),  h = dd>>2
//
// All-fp32 seed path; staging (tid>=96) runs in parallel with the per-block
// trig precompute (tid<64); 2 barriers total.
__global__ __launch_bounds__(256) void sinenet_kernel(
    const float* __restrict__ x,   const float* __restrict__ nlf,
    const float* __restrict__ tau, const float* __restrict__ a,
    const float* __restrict__ phi, const float* __restrict__ i2pi,
    const float* __restrict__ kT,  float* __restrict__ out)
{
    __shared__ __align__(16) float xs[TLEN];
    __shared__ float omgS[NH], cdS[NH], sdS[NH];
    __shared__ float partS[NWARP][NH], partC[NWARP][NH];

    const int sb  = blockIdx.x;
    const int tid = threadIdx.x;
    const int w   = tid >> 5;
    const int l   = tid & 31;

    // threads 96..255: stage x[sb,:] (160 float4 loads)
    if (tid >= 96) {
        const int i = tid - 96;
        const float4 v = reinterpret_cast<const float4*>(x + sb * TLEN)[i];
        reinterpret_cast<float4*>(xs)[i] = v;
    }

    // threads 0..63: per-harmonic omega + accurate sincos(delta), in parallel
    if (tid < NH) {
        const float fF  = expf(__fadd_rn(__fmul_rn(nlf[sb], 0.373288f), 5.02654f));
        const float omg = __fmul_rn(i2pi[4 * tid], fF);   // bit-matches ref's i_f
        omgS[tid] = omg;
        sincosf(omg * T_WAV, &sdS[tid], &cdS[tid]);
    }
    __syncthreads();

    // ---- per-chain seeds, all fp32 ----
    // tsh = kT[last sample of chunk] - tau, with kT computed arithmetically
    const float tv   = tau[sb];
    const float tshL = __fadd_rn(__fmul_rn((float)(w * NT + (NT - 1)), T_WAV), -tv);
    const float om1  = omgS[0];
    // base = om1*tshL mod 2pi as hi/lo pair (exact product split + Cody-Waite)
    float bHi, bLo;
    {
        const float p  = __fmul_rn(om1, tshL);
        const float pe = __fmaf_rn(om1, tshL, -p);        // exact low part
        const float k  = rintf(p * INV2PI);               // k <= ~27
        float r = __fmaf_rn(-k, PI2_HI, p);
        r = __fmaf_rn(-k, PI2_LO, r);
        bHi = r;  bLo = pe;
    }
    float cd[2], sd[2], ce[2], se[2];
    #pragma unroll
    for (int q = 0; q < 2; ++q) {
        const int   h   = l + 32 * q;
        const float Hf  = (float)(h + 1);
        const float omg = omgS[h];
        cd[q] = cdS[h];  sd[q] = sdS[h];
        const float eps = __fmaf_rn(-Hf, om1, omg);       // exact residual
        // psi = Hf*(bHi+bLo) + eps*tshL, Cody-Waite reduced mod 2pi
        const float p   = Hf * bHi;
        const float pe  = __fmaf_rn(Hf, bHi, -p);         // exact low part
        const float plo = __fmaf_rn(Hf, bLo, __fmaf_rn(eps, tshL, pe));
        const float k   = rintf(p * INV2PI);
        float r = __fmaf_rn(-k, PI2_HI, p);
        r = __fmaf_rn(-k, PI2_LO, r) + plo;
        __sincosf(r, &se[q], &ce[q]);
    }

    const u64 twoC = pk2(cd[0] + cd[0], cd[1] + cd[1]);
    const u64 nOne = pk2(-1.0f, -1.0f);
    u64 s1 = 0ull, s2 = 0ull;

    // main loop: 1 LDS.64 + 2 reg-packs + 4 packed fma per 2 samples
    const float2* xp = reinterpret_cast<const float2*>(xs + w * NT);
    #pragma unroll 8
    for (int j = 0; j < NT / 2; ++j) {
        const float2 xv = xp[j];
        const u64 xa = pk2(xv.x, xv.x);
        const u64 t0 = fma2(nOne, s2, xa);
        const u64 n0 = fma2(twoC, s1, t0);  s2 = s1; s1 = n0;
        const u64 xb = pk2(xv.y, xv.y);
        const u64 t1 = fma2(nOne, s2, xb);
        const u64 n1 = fma2(twoC, s1, t1);  s2 = s1; s1 = n1;
    }

    // per-chain extraction: y = s1 - e^{-id} s2, rotate conj(y) by psi_last
    float A0, A1, B0, B1;
    upk2(s1, A0, A1);
    upk2(s2, B0, B1);
    {
        const float Re = __fmaf_rn(-cd[0], B0, A0);
        const float Im = sd[0] * B0;
        partS[w][l] = se[0] * Re - ce[0] * Im;
        partC[w][l] = ce[0] * Re + se[0] * Im;
    }
    {
        const float Re = __fmaf_rn(-cd[1], B1, A1);
        const float Im = sd[1] * B1;
        partS[w][l + 32] = se[1] * Re - ce[1] * Im;
        partC[w][l + 32] = ce[1] * Re + se[1] * Im;
    }
    __syncthreads();

    // fused reduce + epilogue: 64 threads, one harmonic each -> float4 out
    if (tid < NH) {
        const int h = tid;
        float Ss = 0.0f, Cs = 0.0f;
        #pragma unroll
        for (int ww = 0; ww < NWARP; ++ww) {
            Ss += partS[ww][h];
            Cs += partC[ww][h];
        }
        const float4 a4 = reinterpret_cast<const float4*>(a)[h];
        const float4 p4 = reinterpret_cast<const float4*>(phi)[h];
        float4 o;
        float sph, cph;
        __sincosf(p4.x, &sph, &cph);  o.x = a4.x * (cph * Ss + sph * Cs);
        __sincosf(p4.y, &sph, &cph);  o.y = a4.y * (cph * Ss + sph * Cs);
        __sincosf(p4.z, &sph, &cph);  o.z = a4.z * (cph * Ss + sph * Cs);
        __sincosf(p4.w, &sph, &cph);  o.w = a4.w * (cph * Ss + sph * Cs);
        reinterpret_cast<float4*>(out + sb * DDIM)[h] = o;
    }
}

extern "C" void kernel_launch(void* const* d_in, const int* in_sizes, int n_in,
                              void* d_out, int out_size)
{
    const float* x    = (const float*)d_in[0];   // (S,B,1,T)
    const float* nlf  = (const float*)d_in[1];   // (S,B,1,1)
    const float* tau  = (const float*)d_in[2];   // (S,B,1,1)
    const float* a    = (const float*)d_in[3];   // (D,1)
    const float* phi  = (const float*)d_in[4];   // (D,1)
    const float* i2pi = (const float*)d_in[5];   // (D,1)
    const float* kT   = (const float*)d_in[6];   // (1,T)
    float* out = (float*)d_out;                  // (S,B,D)

    sinenet_kernel<<<1024, 256>>>(x, nlf, tau, a, phi, i2pi, kT, out);
}

// round 9
// speedup vs baseline: 1.0586x; 1.0586x over previous
#include <cuda_runtime.h>

#define TLEN  640
#define DDIM  256
#define NH    64              // distinct harmonics (D / NUM_CH)
#define NWARP 8
#define NT    (TLEN / NWARP)  // 80 samples per warp chunk

typedef unsigned long long u64;

__device__ __forceinline__ u64 pk2(float lo, float hi) {
    u64 r; asm("mov.b64 %0, {%1,%2};" : "=l"(r) : "f"(lo), "f"(hi)); return r;
}
__device__ __forceinline__ void upk2(u64 v, float &lo, float &hi) {
    asm("mov.b64 {%0,%1}, %2;" : "=f"(lo), "=f"(hi) : "l"(v));
}
__device__ __forceinline__ u64 fma2(u64 a, u64 b, u64 c) {
    u64 d; asm("fma.rn.f32x2 %0, %1, %2, %3;" : "=l"(d) : "l"(a), "l"(b), "l"(c)); return d;
}

#define INV2PI 0.15915494309189535f
#define PI2_HI 6.28125f                    // 8-bit mantissa: k*PI2_HI exact for k small
#define PI2_LO 1.9353071795864769e-3f
#define T_WAV  6.25e-05f                   // fl(1/16000), matches reference arange*scalar

// fast mod-2pi + MUFU sincos (arg <= ~30 rad -> k exact in PI2_HI product)
__device__ __forceinline__ void fast_sincos_r(float x, float *s, float *c) {
    const float k = rintf(x * INV2PI);
    float r = __fmaf_rn(-k, PI2_HI, x);
    r = __fmaf_rn(-k, PI2_LO, r);
    __sincosf(r, s, c);
}

// Goertzel per (t-chunk, harmonic):  s_n = x_n + 2cos(d)*s_{n-1} - s_{n-2}
// y = s_{N-1} - e^{-id} s_{N-2};  C + iS = e^{i psi_last} * conj(y)
// out[sb,dd] = a[dd] * ( cos(phi)*S_h + sin(phi)*C_h ),  h = dd>>2
//
// Fully per-thread fp32 seed path (no shared trig, no precompute warps):
// seeds overlap the x-staging LDG latency; only 2 cheap barriers per block.
__global__ __launch_bounds__(256) void sinenet_kernel(
    const float* __restrict__ x,   const float* __restrict__ nlf,
    const float* __restrict__ tau, const float* __restrict__ a,
    const float* __restrict__ phi, const float* __restrict__ i2pi,
    const float* __restrict__ kT,  float* __restrict__ out)
{
    __shared__ __align__(16) float xs[TLEN];
    __shared__ float partS[NWARP][NH], partC[NWARP][NH];

    const int sb  = blockIdx.x;
    const int tid = threadIdx.x;
    const int w   = tid >> 5;
    const int l   = tid & 31;

    // stage x[sb,:] (160 float4 loads; issued first, overlapped by seed math)
    if (tid < TLEN / 4) {
        const float4 v = reinterpret_cast<const float4*>(x + sb * TLEN)[tid];
        reinterpret_cast<float4*>(xs)[tid] = v;
    }

    // ---- per-thread seeds, all fp32, no shared ----
    const float fF   = expf(__fadd_rn(__fmul_rn(nlf[sb], 0.373288f), 5.02654f));
    const float tv   = tau[sb];
    const float om1  = __fmul_rn(i2pi[0], fF);
    const float tshL = __fadd_rn(__fmul_rn((float)(w * NT + (NT - 1)), T_WAV), -tv);

    // base = om1*tshL mod 2pi as hi/lo pair (exact product split + Cody-Waite)
    float bHi, bLo;
    {
        const float p  = __fmul_rn(om1, tshL);
        const float pe = __fmaf_rn(om1, tshL, -p);        // exact low part
        const float k  = rintf(p * INV2PI);
        float r = __fmaf_rn(-k, PI2_HI, p);
        r = __fmaf_rn(-k, PI2_LO, r);
        bHi = r;  bLo = pe;
    }

    float cd[2], sd[2], ce[2], se[2];
    #pragma unroll
    for (int q = 0; q < 2; ++q) {
        const int   h   = l + 32 * q;
        const float Hf  = (float)(h + 1);
        const float omg = __fmul_rn(i2pi[4 * h], fF);     // bit-matches ref's i_f
        fast_sincos_r(omg * T_WAV, &sd[q], &cd[q]);       // delta = omg/16000
        const float eps = __fmaf_rn(-Hf, om1, omg);       // exact residual
        // psi = Hf*(bHi+bLo) + eps*tshL, Cody-Waite reduced mod 2pi
        const float p   = Hf * bHi;
        const float pe  = __fmaf_rn(Hf, bHi, -p);         // exact low part
        const float plo = __fmaf_rn(Hf, bLo, __fmaf_rn(eps, tshL, pe));
        const float k   = rintf(p * INV2PI);
        float r = __fmaf_rn(-k, PI2_HI, p);
        r = __fmaf_rn(-k, PI2_LO, r) + plo;
        __sincosf(r, &se[q], &ce[q]);
    }

    const u64 twoC = pk2(cd[0] + cd[0], cd[1] + cd[1]);
    const u64 nOne = pk2(-1.0f, -1.0f);
    u64 s1 = 0ull, s2 = 0ull;

    __syncthreads();   // xs ready

    // main loop: 1 LDS.64 + 2 reg-packs + 4 packed fma per 2 samples
    const float2* xp = reinterpret_cast<const float2*>(xs + w * NT);
    #pragma unroll 8
    for (int j = 0; j < NT / 2; ++j) {
        const float2 xv = xp[j];
        const u64 xa = pk2(xv.x, xv.x);
        const u64 t0 = fma2(nOne, s2, xa);
        const u64 n0 = fma2(twoC, s1, t0);  s2 = s1; s1 = n0;
        const u64 xb = pk2(xv.y, xv.y);
        const u64 t1 = fma2(nOne, s2, xb);
        const u64 n1 = fma2(twoC, s1, t1);  s2 = s1; s1 = n1;
    }

    // per-chain extraction: y = s1 - e^{-id} s2, rotate conj(y) by psi_last
    float A0, A1, B0, B1;
    upk2(s1, A0, A1);
    upk2(s2, B0, B1);
    {
        const float Re = __fmaf_rn(-cd[0], B0, A0);
        const float Im = sd[0] * B0;
        partS[w][l] = se[0] * Re - ce[0] * Im;
        partC[w][l] = ce[0] * Re + se[0] * Im;
    }
    {
        const float Re = __fmaf_rn(-cd[1], B1, A1);
        const float Im = sd[1] * B1;
        partS[w][l + 32] = se[1] * Re - ce[1] * Im;
        partC[w][l + 32] = ce[1] * Re + se[1] * Im;
    }
    __syncthreads();

    // fused reduce + epilogue: 64 threads, one harmonic each -> float4 out
    if (tid < NH) {
        const int h = tid;
        float Ss = 0.0f, Cs = 0.0f;
        #pragma unroll
        for (int ww = 0; ww < NWARP; ++ww) {
            Ss += partS[ww][h];
            Cs += partC[ww][h];
        }
        const float4 a4 = reinterpret_cast<const float4*>(a)[h];
        const float4 p4 = reinterpret_cast<const float4*>(phi)[h];
        float4 o;
        float sph, cph;
        __sincosf(p4.x, &sph, &cph);  o.x = a4.x * (cph * Ss + sph * Cs);
        __sincosf(p4.y, &sph, &cph);  o.y = a4.y * (cph * Ss + sph * Cs);
        __sincosf(p4.z, &sph, &cph);  o.z = a4.z * (cph * Ss + sph * Cs);
        __sincosf(p4.w, &sph, &cph);  o.w = a4.w * (cph * Ss + sph * Cs);
        reinterpret_cast<float4*>(out + sb * DDIM)[h] = o;
    }
}

extern "C" void kernel_launch(void* const* d_in, const int* in_sizes, int n_in,
                              void* d_out, int out_size)
{
    const float* x    = (const float*)d_in[0];   // (S,B,1,T)
    const float* nlf  = (const float*)d_in[1];   // (S,B,1,1)
    const float* tau  = (const float*)d_in[2];   // (S,B,1,1)
    const float* a    = (const float*)d_in[3];   // (D,1)
    const float* phi  = (const float*)d_in[4];   // (D,1)
    const float* i2pi = (const float*)d_in[5];   // (D,1)
    const float* kT   = (const float*)d_in[6];   // (1,T)
    float* out = (float*)d_out;                  // (S,B,D)

    sinenet_kernel<<<1024, 256>>>(x, nlf, tau, a, phi, i2pi, kT, out);
}